// round 11
// baseline (speedup 1.0000x reference)
#include <cuda_runtime.h>

#define Bq  256
#define Tq  2000
#define Fq  80
#define Hq  64
#define G3q 192
#define Oq  29

// Precomputed layer-0 input projection: gx0[b][t][g] (393 MB static device scratch)
__device__ float g_gx0[(size_t)Bq * Tq * G3q];

// MUFU.TANH (sm_75+)
__device__ __forceinline__ float tanha(float x) {
    float y;
    asm("tanh.approx.f32 %0, %1;" : "=f"(y) : "f"(x));
    return y;
}
__device__ __forceinline__ float siga(float x) {
    return fmaf(tanha(0.5f * x), 0.5f, 0.5f);
}

// Blackwell packed f32x2 FMA (PTX-only; ptxas never auto-fuses)
__device__ __forceinline__ float2 ffma2(float2 a, float2 b, float2 c) {
    float2 d;
    asm("fma.rn.f32x2 %0, %1, %2, %3;"
        : "=l"(*reinterpret_cast<unsigned long long*>(&d))
        : "l"(*reinterpret_cast<unsigned long long*>(&a)),
          "l"(*reinterpret_cast<unsigned long long*>(&b)),
          "l"(*reinterpret_cast<unsigned long long*>(&c)));
    return d;
}

// ---------------------------------------------------------------------------
// Kernel 1: gx0 = x @ W_ih0^T + b_ih0  (identical to R8: register weight rows,
// 4 timesteps in flight, natural-layout x staging).
// ---------------------------------------------------------------------------
__global__ __launch_bounds__(192, 2) void gx0_kernel(
    const float* __restrict__ x,
    const float* __restrict__ W_ih0,
    const float* __restrict__ b_ih0)
{
    __shared__ float xs[40 * Fq];          // 12.8 KB, [t][f] natural layout

    const int g = threadIdx.x;             // gate 0..191
    const int b = blockIdx.x;              // batch

    float2 wv[40];
    {
        const float2* Wp = reinterpret_cast<const float2*>(W_ih0 + g * Fq);
        #pragma unroll
        for (int k = 0; k < 40; ++k) wv[k] = Wp[k];
    }
    const float bias = b_ih0[g];

    const float4* xg = reinterpret_cast<const float4*>(x + (size_t)b * Tq * Fq);
    float* outp = g_gx0 + (size_t)b * Tq * G3q + g;

    for (int c = 0; c < 50; ++c) {
        const float4* src = xg + c * (40 * Fq / 4);
        #pragma unroll 1
        for (int i = g; i < 800; i += 192)
            reinterpret_cast<float4*>(xs)[i] = src[i];
        __syncthreads();

        #pragma unroll 1
        for (int tg = 0; tg < 10; ++tg) {
            const float4* x0 = reinterpret_cast<const float4*>(&xs[(tg * 4 + 0) * Fq]);
            const float4* x1 = reinterpret_cast<const float4*>(&xs[(tg * 4 + 1) * Fq]);
            const float4* x2 = reinterpret_cast<const float4*>(&xs[(tg * 4 + 2) * Fq]);
            const float4* x3 = reinterpret_cast<const float4*>(&xs[(tg * 4 + 3) * Fq]);
            float2 a0 = make_float2(bias, 0.0f);
            float2 a1 = make_float2(bias, 0.0f);
            float2 a2 = make_float2(bias, 0.0f);
            float2 a3 = make_float2(bias, 0.0f);
            #pragma unroll
            for (int k = 0; k < 20; ++k) {
                float2 wlo = wv[2 * k], whi = wv[2 * k + 1];
                float4 v0 = x0[k];
                a0 = ffma2(wlo, make_float2(v0.x, v0.y), a0);
                a0 = ffma2(whi, make_float2(v0.z, v0.w), a0);
                float4 v1 = x1[k];
                a1 = ffma2(wlo, make_float2(v1.x, v1.y), a1);
                a1 = ffma2(whi, make_float2(v1.z, v1.w), a1);
                float4 v2 = x2[k];
                a2 = ffma2(wlo, make_float2(v2.x, v2.y), a2);
                a2 = ffma2(whi, make_float2(v2.z, v2.w), a2);
                float4 v3 = x3[k];
                a3 = ffma2(wlo, make_float2(v3.x, v3.y), a3);
                a3 = ffma2(whi, make_float2(v3.z, v3.w), a3);
            }
            int tbase = c * 40 + tg * 4;
            outp[(size_t)(tbase + 0) * G3q] = a0.x + a0.y;
            outp[(size_t)(tbase + 1) * G3q] = a1.x + a1.y;
            outp[(size_t)(tbase + 2) * G3q] = a2.x + a2.y;
            outp[(size_t)(tbase + 3) * G3q] = a3.x + a3.y;
        }
        __syncthreads();
    }
}

// ---------------------------------------------------------------------------
// Kernel 2: fused 2-layer GRU + FC — 768 threads (24 warps) for latency hiding.
//   tid   0..255: L0, j = tid>>2, seg = tid&3   (16-float K window of h0)
//   tid 256..767: L1, j = (tid-256)>>3, seg = (tid-256)&7
//                 (16-float window of concat [h0;h1]; seg<4 = W_ih1, >=4 = W_hh1)
// Reductions: L0 xor1+xor2; L1 xor1+xor2 (within side) then xor4 (r/z sum
// across sides; n-dot exchanged). Act threads: seg==batch (0/1); h state in
// 8x(16+4) padded SMEM segments — seg starts hit disjoint bank quads.
// ---------------------------------------------------------------------------
__global__ __launch_bounds__(768, 1) void rnn_kernel(
    const float* __restrict__ h_in,
    const float* __restrict__ W_hh0, const float* __restrict__ b_hh0,
    const float* __restrict__ W_ih1, const float* __restrict__ W_hh1,
    const float* __restrict__ b_ih1, const float* __restrict__ b_hh1,
    const float* __restrict__ W_fc,  const float* __restrict__ b_fc,
    float* __restrict__ out, int write_hidden)
{
    // [parity][batch][seg of concat [h0;h1]][16 + 4 pad]
    __shared__ float hbuf[2][2][8][20];

    const int tid  = threadIdx.x;
    const int b0   = blockIdx.x * 2;
    const bool isL0 = tid < 256;
    int j, seg;
    if (isL0) { j = tid >> 2; seg = tid & 3; }
    else      { int t = tid - 256; j = t >> 3; seg = t & 7; }

    // --- weight windows (r,z,n) -> registers: 4 float4 per gate ---
    float4 wR[4], wZ[4], wN[4];
    {
        const float4* W;
        int k0;
        if (isL0)          { W = (const float4*)W_hh0; k0 = seg * 4; }
        else if (seg < 4)  { W = (const float4*)W_ih1; k0 = seg * 4; }
        else               { W = (const float4*)W_hh1; k0 = (seg - 4) * 4; }
        #pragma unroll
        for (int k = 0; k < 4; ++k) {
            wR[k] = W[(j      ) * 16 + k0 + k];
            wZ[k] = W[(64 + j ) * 16 + k0 + k];
            wN[k] = W[(128 + j) * 16 + k0 + k];
        }
    }
    // --- biases (act role) ---
    float bR, bZ, bNi = 0.0f, bNh;
    if (isL0) {
        bR = b_hh0[j]; bZ = b_hh0[64 + j]; bNh = b_hh0[128 + j];
    } else {
        bR  = b_ih1[j] + b_hh1[j];
        bZ  = b_ih1[64 + j] + b_hh1[64 + j];
        bNi = b_ih1[128 + j]; bNh = b_hh1[128 + j];
    }

    // --- init: h0^0 -> parity0 segs0-3 ; h1^0 -> parity1 segs4-7 ---
    if (tid < 256) {
        int b = tid >> 7, idx = tid & 127;
        if (idx < 64) {
            hbuf[0][b][idx >> 4][idx & 15] = h_in[(b0 + b) * Hq + idx];
            hbuf[1][b][idx >> 4][idx & 15] = 0.0f;
        } else {
            int jj = idx - 64;
            hbuf[1][b][4 + (jj >> 4)][jj & 15] = h_in[Bq * Hq + (b0 + b) * Hq + jj];
            hbuf[0][b][4 + (jj >> 4)][jj & 15] = 0.0f;
        }
    }
    __syncthreads();

    // gx stream (L0 act threads: batch = seg, seg<2)
    const float* gxp = g_gx0 + (size_t)(b0 + (seg & 1)) * Tq * G3q;
    float gxR = 0.0f, gxZ = 0.0f, gxN = 0.0f;
    if (isL0 && seg < 2) { gxR = gxp[j]; gxZ = gxp[64 + j]; gxN = gxp[128 + j]; }

    // previous h element owned by act threads
    float hprev = 0.0f;
    if (isL0 && seg < 2)        hprev = h_in[(b0 + seg) * Hq + j];
    else if (!isL0 && seg < 2)  hprev = h_in[Bq * Hq + (b0 + seg) * Hq + j];

    for (int i = 0; i <= Tq; ++i) {
        const int p = i & 1;

        // prefetch next step's gx (L0 act threads only; a full step of slack)
        float nR = 0.0f, nZ = 0.0f, nN = 0.0f;
        if (isL0 && seg < 2 && i + 1 < Tq) {
            const float* gq = gxp + (size_t)(i + 1) * G3q;
            nR = __ldg(gq + j); nZ = __ldg(gq + 64 + j); nN = __ldg(gq + 128 + j);
        }

        // --- partial dots over this thread's 16-float window, both batches ---
        const float4* u4 = (const float4*)&hbuf[p][0][seg][0];
        const float4* v4 = (const float4*)&hbuf[p][1][seg][0];
        float2 aR0 = {0,0}, aZ0 = {0,0}, aN0 = {0,0};
        float2 aR1 = {0,0}, aZ1 = {0,0}, aN1 = {0,0};
        #pragma unroll
        for (int k = 0; k < 4; ++k) {
            float4 u = u4[k], v = v4[k];
            float2 ulo = make_float2(u.x, u.y), uhi = make_float2(u.z, u.w);
            float2 vlo = make_float2(v.x, v.y), vhi = make_float2(v.z, v.w);
            float2 rlo = make_float2(wR[k].x, wR[k].y), rhi = make_float2(wR[k].z, wR[k].w);
            float2 zlo = make_float2(wZ[k].x, wZ[k].y), zhi = make_float2(wZ[k].z, wZ[k].w);
            float2 nlo = make_float2(wN[k].x, wN[k].y), nhi = make_float2(wN[k].z, wN[k].w);
            aR0 = ffma2(rlo, ulo, aR0);  aR0 = ffma2(rhi, uhi, aR0);
            aZ0 = ffma2(zlo, ulo, aZ0);  aZ0 = ffma2(zhi, uhi, aZ0);
            aN0 = ffma2(nlo, ulo, aN0);  aN0 = ffma2(nhi, uhi, aN0);
            aR1 = ffma2(rlo, vlo, aR1);  aR1 = ffma2(rhi, vhi, aR1);
            aZ1 = ffma2(zlo, vlo, aZ1);  aZ1 = ffma2(zhi, vhi, aZ1);
            aN1 = ffma2(nlo, vlo, aN1);  aN1 = ffma2(nhi, vhi, aN1);
        }
        float dR0 = aR0.x + aR0.y, dZ0 = aZ0.x + aZ0.y, dN0 = aN0.x + aN0.y;
        float dR1 = aR1.x + aR1.y, dZ1 = aZ1.x + aZ1.y, dN1 = aN1.x + aN1.y;

        if (isL0) {
            // full sum over 4 segs (xor1 + xor2)
            dR0 += __shfl_xor_sync(0xffffffffu, dR0, 1);
            dZ0 += __shfl_xor_sync(0xffffffffu, dZ0, 1);
            dN0 += __shfl_xor_sync(0xffffffffu, dN0, 1);
            dR1 += __shfl_xor_sync(0xffffffffu, dR1, 1);
            dZ1 += __shfl_xor_sync(0xffffffffu, dZ1, 1);
            dN1 += __shfl_xor_sync(0xffffffffu, dN1, 1);
            dR0 += __shfl_xor_sync(0xffffffffu, dR0, 2);
            dZ0 += __shfl_xor_sync(0xffffffffu, dZ0, 2);
            dN0 += __shfl_xor_sync(0xffffffffu, dN0, 2);
            dR1 += __shfl_xor_sync(0xffffffffu, dR1, 2);
            dZ1 += __shfl_xor_sync(0xffffffffu, dZ1, 2);
            dN1 += __shfl_xor_sync(0xffffffffu, dN1, 2);
            if (i < Tq && seg < 2) {
                float dR = seg ? dR1 : dR0;
                float dZ = seg ? dZ1 : dZ0;
                float dN = seg ? dN1 : dN0;
                float r = siga(gxR + dR + bR);
                float z = siga(gxZ + dZ + bZ);
                float n = tanha(fmaf(r, dN + bNh, gxN));   // gxN includes b_ih0
                float hn = (1.0f - z) * n + z * hprev;
                hprev = hn;
                hbuf[p ^ 1][seg][j >> 4][j & 15] = hn;
            }
            gxR = nR; gxZ = nZ; gxN = nN;
        } else {
            // xor1 + xor2: combine within side (segs {0..3} x-side, {4..7} h-side)
            dR0 += __shfl_xor_sync(0xffffffffu, dR0, 1);
            dZ0 += __shfl_xor_sync(0xffffffffu, dZ0, 1);
            dN0 += __shfl_xor_sync(0xffffffffu, dN0, 1);
            dR1 += __shfl_xor_sync(0xffffffffu, dR1, 1);
            dZ1 += __shfl_xor_sync(0xffffffffu, dZ1, 1);
            dN1 += __shfl_xor_sync(0xffffffffu, dN1, 1);
            dR0 += __shfl_xor_sync(0xffffffffu, dR0, 2);
            dZ0 += __shfl_xor_sync(0xffffffffu, dZ0, 2);
            dN0 += __shfl_xor_sync(0xffffffffu, dN0, 2);
            dR1 += __shfl_xor_sync(0xffffffffu, dR1, 2);
            dZ1 += __shfl_xor_sync(0xffffffffu, dZ1, 2);
            dN1 += __shfl_xor_sync(0xffffffffu, dN1, 2);
            // xor4: sum r/z across sides; exchange opposite side's n-dot
            float oR0 = __shfl_xor_sync(0xffffffffu, dR0, 4);
            float oZ0 = __shfl_xor_sync(0xffffffffu, dZ0, 4);
            float oN0 = __shfl_xor_sync(0xffffffffu, dN0, 4);
            float oR1 = __shfl_xor_sync(0xffffffffu, dR1, 4);
            float oZ1 = __shfl_xor_sync(0xffffffffu, dZ1, 4);
            float oN1 = __shfl_xor_sync(0xffffffffu, dN1, 4);
            dR0 += oR0; dZ0 += oZ0;
            dR1 += oR1; dZ1 += oZ1;
            // seg<4: dN = x-side, oN = h-side
            if (i > 0 && seg < 2) {
                float dR  = seg ? dR1 : dR0;
                float dZ  = seg ? dZ1 : dZ0;
                float dNx = seg ? dN1 : dN0;
                float dNh = seg ? oN1 : oN0;
                float r = siga(dR + bR);
                float z = siga(dZ + bZ);
                float n = tanha(fmaf(r, dNh + bNh, dNx + bNi));
                float hn = (1.0f - z) * n + z * hprev;
                hprev = hn;
                hbuf[p ^ 1][seg][4 + (j >> 4)][j & 15] = hn;
            }
        }
        __syncthreads();   // publish h0^{i+1}, h1^{i} for next iteration
    }

    // ---- epilogue: h0 final in parity (Tq&1)=0; h1 final in parity 1 ----
    if (write_hidden && tid < 2 * Hq) {
        int b = tid >> 6, jj = tid & 63;
        out[Bq * Oq + (b0 + b) * Hq + jj]           = hbuf[0][b][jj >> 4][jj & 15];
        out[Bq * Oq + Bq * Hq + (b0 + b) * Hq + jj] = hbuf[1][b][4 + (jj >> 4)][jj & 15];
    }
    if (tid < 2 * Oq) {
        int b = tid / Oq, o = tid - b * Oq;
        float acc = b_fc[o];
        #pragma unroll
        for (int jj = 0; jj < Hq; ++jj)
            acc = fmaf(fmaxf(hbuf[1][b][4 + (jj >> 4)][jj & 15], 0.0f),
                       __ldg(&W_fc[o * Hq + jj]), acc);
        out[(b0 + b) * Oq + o] = acc;
    }
}

// ---------------------------------------------------------------------------
extern "C" void kernel_launch(void* const* d_in, const int* in_sizes, int n_in,
                              void* d_out, int out_size) {
    const float* x     = (const float*)d_in[0];
    const float* h     = (const float*)d_in[1];
    const float* W_ih0 = (const float*)d_in[2];
    const float* W_hh0 = (const float*)d_in[3];
    const float* b_ih0 = (const float*)d_in[4];
    const float* b_hh0 = (const float*)d_in[5];
    const float* W_ih1 = (const float*)d_in[6];
    const float* W_hh1 = (const float*)d_in[7];
    const float* b_ih1 = (const float*)d_in[8];
    const float* b_hh1 = (const float*)d_in[9];
    const float* W_fc  = (const float*)d_in[10];
    const float* b_fc  = (const float*)d_in[11];
    float* out = (float*)d_out;

    gx0_kernel<<<Bq, 192>>>(x, W_ih0, b_ih0);

    int write_hidden = (out_size >= Bq * Oq + 2 * Bq * Hq) ? 1 : 0;
    rnn_kernel<<<Bq / 2, 768>>>(h, W_hh0, b_hh0,
                                W_ih1, W_hh1, b_ih1, b_hh1,
                                W_fc, b_fc, out, write_hidden);
}

// round 14
// speedup vs baseline: 1.1283x; 1.1283x over previous
#include <cuda_runtime.h>

#define Bq  256
#define Tq  2000
#define Fq  80
#define Hq  64
#define G3q 192
#define Oq  29

// layer-0 input projection scratch: gx0[b][t][g] (393 MB static device alloc)
__device__ float g_gx0[(size_t)Bq * Tq * G3q];

// MUFU.TANH (sm_75+)
__device__ __forceinline__ float tanha(float x) {
    float y;
    asm("tanh.approx.f32 %0, %1;" : "=f"(y) : "f"(x));
    return y;
}
__device__ __forceinline__ float siga(float x) {
    return fmaf(tanha(0.5f * x), 0.5f, 0.5f);
}

// Blackwell packed f32x2 FMA (PTX-only; ptxas never auto-fuses)
__device__ __forceinline__ float2 ffma2(float2 a, float2 b, float2 c) {
    float2 d;
    asm("fma.rn.f32x2 %0, %1, %2, %3;"
        : "=l"(*reinterpret_cast<unsigned long long*>(&d))
        : "l"(*reinterpret_cast<unsigned long long*>(&a)),
          "l"(*reinterpret_cast<unsigned long long*>(&b)),
          "l"(*reinterpret_cast<unsigned long long*>(&c)));
    return d;
}

// ---------------------------------------------------------------------------
// SINGLE fused kernel: 2-layer GRU + FC, with the layer-0 input projection
// (gx0 GEMM) computed in-loop 5..8 steps ahead of consumption in the idle
// issue slots of the recurrence.
// Recurrence core (R7 winner, verbatim indexing):
//   tid   0..127: L0, j = tid>>1, seg = tid&1   (K half seg -> hbuf quarter seg)
//   tid 128..383: L1, j = (tid-128)>>2, seg = (tid-128)&3 (concat quarter seg)
// gx producer role (all threads): gxg = tid%192 (gate), gxb = tid/192 (batch);
// window m = i>>2 computes t0 = 8+4m over 4 phases (5 float4-k per step).
// Dynamic SMEM: W_ih0 transposed [k4=20][g=192] float4 (61440B) +
//               x double-buffer [2][2][16][20] float4 (20480B).
// ---------------------------------------------------------------------------
__global__ __launch_bounds__(384, 1) void rnn_kernel(
    const float* __restrict__ x,
    const float* __restrict__ h_in,
    const float* __restrict__ W_ih0, const float* __restrict__ b_ih0,
    const float* __restrict__ W_hh0, const float* __restrict__ b_hh0,
    const float* __restrict__ W_ih1, const float* __restrict__ W_hh1,
    const float* __restrict__ b_ih1, const float* __restrict__ b_hh1,
    const float* __restrict__ W_fc,  const float* __restrict__ b_fc,
    float* __restrict__ out, int write_hidden)
{
    extern __shared__ float dynsm[];
    float4* w4s = reinterpret_cast<float4*>(dynsm);          // [20][192] float4
    float4* xs4 = w4s + 20 * 192;                            // [2][2][16][20] float4
    __shared__ float hbuf[2][2][4][40];  // [parity][batch][quarter][32+8 pad]

    const int tid  = threadIdx.x;
    const int b0   = blockIdx.x * 2;
    const bool isL0 = tid < 128;
    int j, seg;
    if (isL0) { j = tid >> 1; seg = tid & 1; }
    else      { int t = tid - 128; j = t >> 2; seg = t & 3; }

    // gx producer identity: warps 0-5 -> batch 0, warps 6-11 -> batch 1
    const int gxg = tid % 192;
    const int gxb = tid / 192;
    const float bgx = b_ih0[gxg];
    float* gxout = g_gx0 + (size_t)(b0 + gxb) * Tq * G3q + gxg;
    const float4* x4g = reinterpret_cast<const float4*>(x) +
                        (size_t)(b0 + gxb) * Tq * 20;

    // --- recurrence weight windows (r,z,n) -> registers ---
    float4 wR[8], wZ[8], wN[8];
    {
        const float4* W;
        int k0;
        if (isL0)          { W = (const float4*)W_hh0; k0 = seg * 8; }
        else if (seg < 2)  { W = (const float4*)W_ih1; k0 = seg * 8; }
        else               { W = (const float4*)W_hh1; k0 = (seg - 2) * 8; }
        #pragma unroll
        for (int k = 0; k < 8; ++k) {
            wR[k] = W[(j      ) * 16 + k0 + k];
            wZ[k] = W[(64 + j ) * 16 + k0 + k];
            wN[k] = W[(128 + j) * 16 + k0 + k];
        }
    }
    float bR, bZ, bNi = 0.0f, bNh;
    if (isL0) {
        bR = b_hh0[j]; bZ = b_hh0[64 + j]; bNh = b_hh0[128 + j];
    } else {
        bR  = b_ih1[j] + b_hh1[j];
        bZ  = b_ih1[64 + j] + b_hh1[64 + j];
        bNi = b_ih1[128 + j]; bNh = b_hh1[128 + j];
    }

    // --- cooperative loads: W_ih0 transposed into SMEM; h state init ---
    for (int idx = tid; idx < 20 * 192; idx += 384) {
        int k4 = idx / 192, g = idx % 192;
        w4s[idx] = reinterpret_cast<const float4*>(W_ih0)[g * 20 + k4];
    }
    if (tid < 256) {
        int b = tid >> 7, idx = tid & 127;
        if (idx < 64) {
            hbuf[0][b][idx >> 5][idx & 31] = h_in[(b0 + b) * Hq + idx];
            hbuf[1][b][idx >> 5][idx & 31] = 0.0f;
        } else {
            int jj = idx - 64;
            hbuf[1][b][2 + (jj >> 5)][jj & 31] = h_in[Bq * Hq + (b0 + b) * Hq + jj];
            hbuf[0][b][2 + (jj >> 5)][jj & 31] = 0.0f;
        }
    }
    __syncthreads();   // w4s + hbuf published

    // --- prologue: gx for t in [0,8) from GMEM x; stage x chunk 0 (t 8..24) ---
    for (int t = 0; t < 8; ++t) {
        float2 a = make_float2(bgx, 0.0f);
        #pragma unroll
        for (int k4 = 0; k4 < 20; ++k4) {
            float4 v = __ldg(&x4g[t * 20 + k4]);
            float4 w = w4s[k4 * 192 + gxg];
            a = ffma2(make_float2(w.x, w.y), make_float2(v.x, v.y), a);
            a = ffma2(make_float2(w.z, w.w), make_float2(v.z, v.w), a);
        }
        gxout[(size_t)t * G3q] = a.x + a.y;
    }
    for (int e = tid; e < 640; e += 384) {       // chunk 0 -> buf 0
        int b = e / 320, r = e - b * 320, t = r / 20, k4 = r - t * 20;
        xs4[((0 * 2 + b) * 16 + t) * 20 + k4] =
            __ldg(reinterpret_cast<const float4*>(x) +
                  ((size_t)(b0 + b) * Tq + 8 + t) * 20 + k4);
    }
    __syncthreads();   // prologue gx + chunk 0 visible

    // gx consumer init (L0 act threads: batch = seg)
    const float* gxp = g_gx0 + (size_t)(b0 + (seg & 1)) * Tq * G3q;
    float gxR = 0.0f, gxZ = 0.0f, gxN = 0.0f;
    if (isL0 && seg < 2) { gxR = gxp[j]; gxZ = gxp[64 + j]; gxN = gxp[128 + j]; }

    float hprev = 0.0f;
    if (isL0 && seg < 2)        hprev = h_in[(b0 + seg) * Hq + j];
    else if (!isL0 && seg < 2)  hprev = h_in[Bq * Hq + (b0 + seg) * Hq + j];

    float2 gacc[4];

    for (int i = 0; i <= Tq; ++i) {
        const int p = i & 1;

        // ---- x staging: at step 16c stage chunk c+1 (t in [24+16c, 40+16c)) ----
        if ((i & 15) == 0) {
            int chunk = (i >> 4) + 1;
            int tbase = 8 + (chunk << 4);
            if (tbase < Tq) {
                int buf = chunk & 1;
                for (int e = tid; e < 640; e += 384) {
                    int b = e / 320, r = e - b * 320, t = r / 20, k4 = r - t * 20;
                    int tg = tbase + t;
                    if (tg < Tq)
                        xs4[((buf * 2 + b) * 16 + t) * 20 + k4] =
                            __ldg(reinterpret_cast<const float4*>(x) +
                                  ((size_t)(b0 + b) * Tq + tg) * 20 + k4);
                }
            }
        }

        // ---- gx production: window m=i>>2 -> t0=8+4m, phase i&3 (5 k4 each) ----
        if (i < 1992) {
            const int ph   = i & 3;
            const int xbuf = (i >> 4) & 1;
            const int tloc = i & 12;           // 4*(m&3)
            if (ph == 0) {
                #pragma unroll
                for (int dt = 0; dt < 4; ++dt) gacc[dt] = make_float2(bgx, 0.0f);
            }
            const float4* xr = xs4 + ((xbuf * 2 + gxb) * 16 + tloc) * 20 + ph * 5;
            const float4* wp = w4s + ph * 5 * 192 + gxg;
            #pragma unroll
            for (int k4 = 0; k4 < 5; ++k4) {
                float4 w = wp[k4 * 192];
                float2 wlo = make_float2(w.x, w.y), whi = make_float2(w.z, w.w);
                #pragma unroll
                for (int dt = 0; dt < 4; ++dt) {
                    float4 v = xr[dt * 20 + k4];
                    gacc[dt] = ffma2(wlo, make_float2(v.x, v.y), gacc[dt]);
                    gacc[dt] = ffma2(whi, make_float2(v.z, v.w), gacc[dt]);
                }
            }
            if (ph == 3) {
                int t0 = 8 + (i & ~3);
                #pragma unroll
                for (int dt = 0; dt < 4; ++dt)
                    gxout[(size_t)(t0 + dt) * G3q] = gacc[dt].x + gacc[dt].y;
            }
        }

        // ---- consumer prefetch of gx[i+1] (plain loads: same-block producer) ----
        float nR = 0.0f, nZ = 0.0f, nN = 0.0f;
        if (isL0 && seg < 2 && i + 1 < Tq) {
            const float* gq = gxp + (size_t)(i + 1) * G3q;
            nR = gq[j]; nZ = gq[64 + j]; nN = gq[128 + j];
        }

        // ---- recurrence dots (R7 core, verbatim): quarter seg, 8 float4 ----
        const float4* u4 = (const float4*)&hbuf[p][0][seg][0];
        const float4* v4 = (const float4*)&hbuf[p][1][seg][0];
        float2 aR0 = {0,0}, aZ0 = {0,0}, aN0 = {0,0};
        float2 aR1 = {0,0}, aZ1 = {0,0}, aN1 = {0,0};
        #pragma unroll
        for (int k = 0; k < 8; ++k) {
            float4 u = u4[k], v = v4[k];
            float2 ulo = make_float2(u.x, u.y), uhi = make_float2(u.z, u.w);
            float2 vlo = make_float2(v.x, v.y), vhi = make_float2(v.z, v.w);
            float2 rlo = make_float2(wR[k].x, wR[k].y), rhi = make_float2(wR[k].z, wR[k].w);
            float2 zlo = make_float2(wZ[k].x, wZ[k].y), zhi = make_float2(wZ[k].z, wZ[k].w);
            float2 nlo = make_float2(wN[k].x, wN[k].y), nhi = make_float2(wN[k].z, wN[k].w);
            aR0 = ffma2(rlo, ulo, aR0);  aR0 = ffma2(rhi, uhi, aR0);
            aZ0 = ffma2(zlo, ulo, aZ0);  aZ0 = ffma2(zhi, uhi, aZ0);
            aN0 = ffma2(nlo, ulo, aN0);  aN0 = ffma2(nhi, uhi, aN0);
            aR1 = ffma2(rlo, vlo, aR1);  aR1 = ffma2(rhi, vhi, aR1);
            aZ1 = ffma2(zlo, vlo, aZ1);  aZ1 = ffma2(zhi, vhi, aZ1);
            aN1 = ffma2(nlo, vlo, aN1);  aN1 = ffma2(nhi, vhi, aN1);
        }
        float dR0 = aR0.x + aR0.y, dZ0 = aZ0.x + aZ0.y, dN0 = aN0.x + aN0.y;
        float dR1 = aR1.x + aR1.y, dZ1 = aZ1.x + aZ1.y, dN1 = aN1.x + aN1.y;

        if (isL0) {
            dR0 += __shfl_xor_sync(0xffffffffu, dR0, 1);
            dZ0 += __shfl_xor_sync(0xffffffffu, dZ0, 1);
            dN0 += __shfl_xor_sync(0xffffffffu, dN0, 1);
            dR1 += __shfl_xor_sync(0xffffffffu, dR1, 1);
            dZ1 += __shfl_xor_sync(0xffffffffu, dZ1, 1);
            dN1 += __shfl_xor_sync(0xffffffffu, dN1, 1);
            if (i < Tq) {
                float dR = seg ? dR1 : dR0;
                float dZ = seg ? dZ1 : dZ0;
                float dN = seg ? dN1 : dN0;
                float r = siga(gxR + dR + bR);
                float z = siga(gxZ + dZ + bZ);
                float n = tanha(fmaf(r, dN + bNh, gxN));   // gxN includes b_ih0
                float hn = (1.0f - z) * n + z * hprev;
                hprev = hn;
                hbuf[p ^ 1][seg][j >> 5][j & 31] = hn;
            }
            gxR = nR; gxZ = nZ; gxN = nN;
        } else {
            dR0 += __shfl_xor_sync(0xffffffffu, dR0, 1);
            dZ0 += __shfl_xor_sync(0xffffffffu, dZ0, 1);
            dN0 += __shfl_xor_sync(0xffffffffu, dN0, 1);
            dR1 += __shfl_xor_sync(0xffffffffu, dR1, 1);
            dZ1 += __shfl_xor_sync(0xffffffffu, dZ1, 1);
            dN1 += __shfl_xor_sync(0xffffffffu, dN1, 1);
            float oR0 = __shfl_xor_sync(0xffffffffu, dR0, 2);
            float oZ0 = __shfl_xor_sync(0xffffffffu, dZ0, 2);
            float oN0 = __shfl_xor_sync(0xffffffffu, dN0, 2);
            float oR1 = __shfl_xor_sync(0xffffffffu, dR1, 2);
            float oZ1 = __shfl_xor_sync(0xffffffffu, dZ1, 2);
            float oN1 = __shfl_xor_sync(0xffffffffu, dN1, 2);
            dR0 += oR0; dZ0 += oZ0;
            dR1 += oR1; dZ1 += oZ1;
            if (i > 0 && seg < 2) {
                float dR  = seg ? dR1 : dR0;
                float dZ  = seg ? dZ1 : dZ0;
                float dNx = seg ? dN1 : dN0;
                float dNh = seg ? oN1 : oN0;
                float r = siga(dR + bR);
                float z = siga(dZ + bZ);
                float n = tanha(fmaf(r, dNh + bNh, dNx + bNi));
                float hn = (1.0f - z) * n + z * hprev;
                hprev = hn;
                hbuf[p ^ 1][seg][2 + (j >> 5)][j & 31] = hn;
            }
        }
        __syncthreads();   // h handoff + gx/x staging visibility
    }

    // ---- epilogue ----
    if (write_hidden && tid < 2 * Hq) {
        int b = tid >> 6, jj = tid & 63;
        out[Bq * Oq + (b0 + b) * Hq + jj]           = hbuf[0][b][jj >> 5][jj & 31];
        out[Bq * Oq + Bq * Hq + (b0 + b) * Hq + jj] = hbuf[1][b][2 + (jj >> 5)][jj & 31];
    }
    if (tid < 2 * Oq) {
        int b = tid / Oq, o = tid - b * Oq;
        float acc = b_fc[o];
        #pragma unroll
        for (int jj = 0; jj < Hq; ++jj)
            acc = fmaf(fmaxf(hbuf[1][b][2 + (jj >> 5)][jj & 31], 0.0f),
                       __ldg(&W_fc[o * Hq + jj]), acc);
        out[(b0 + b) * Oq + o] = acc;
    }
}

// ---------------------------------------------------------------------------
extern "C" void kernel_launch(void* const* d_in, const int* in_sizes, int n_in,
                              void* d_out, int out_size) {
    const float* x     = (const float*)d_in[0];
    const float* h     = (const float*)d_in[1];
    const float* W_ih0 = (const float*)d_in[2];
    const float* W_hh0 = (const float*)d_in[3];
    const float* b_ih0 = (const float*)d_in[4];
    const float* b_hh0 = (const float*)d_in[5];
    const float* W_ih1 = (const float*)d_in[6];
    const float* W_hh1 = (const float*)d_in[7];
    const float* b_ih1 = (const float*)d_in[8];
    const float* b_hh1 = (const float*)d_in[9];
    const float* W_fc  = (const float*)d_in[10];
    const float* b_fc  = (const float*)d_in[11];
    float* out = (float*)d_out;

    const int dynsmem = (20 * 192 * 4 + 2 * 2 * 16 * 20 * 4) * (int)sizeof(float); // 81,920 B
    cudaFuncSetAttribute(rnn_kernel, cudaFuncAttributeMaxDynamicSharedMemorySize, dynsmem);

    int write_hidden = (out_size >= Bq * Oq + 2 * Bq * Hq) ? 1 : 0;
    rnn_kernel<<<Bq / 2, 384, dynsmem>>>(x, h, W_ih0, b_ih0, W_hh0, b_hh0,
                                         W_ih1, W_hh1, b_ih1, b_hh1,
                                         W_fc, b_fc, out, write_hidden);
}

// round 15
// speedup vs baseline: 1.1715x; 1.0383x over previous
#include <cuda_runtime.h>

#define Bq  256
#define Tq  2000
#define Fq  80
#define Hq  64
#define G3q 192
#define Oq  29

// Precomputed layer-0 input projection: gx0[b][t][g] (393 MB static device scratch)
__device__ float g_gx0[(size_t)Bq * Tq * G3q];

// MUFU.TANH (sm_75+)
__device__ __forceinline__ float tanha(float x) {
    float y;
    asm("tanh.approx.f32 %0, %1;" : "=f"(y) : "f"(x));
    return y;
}
__device__ __forceinline__ float siga(float x) {
    return fmaf(tanha(0.5f * x), 0.5f, 0.5f);
}

// Blackwell packed f32x2 FMA (PTX-only; ptxas never auto-fuses)
__device__ __forceinline__ float2 ffma2(float2 a, float2 b, float2 c) {
    float2 d;
    asm("fma.rn.f32x2 %0, %1, %2, %3;"
        : "=l"(*reinterpret_cast<unsigned long long*>(&d))
        : "l"(*reinterpret_cast<unsigned long long*>(&a)),
          "l"(*reinterpret_cast<unsigned long long*>(&b)),
          "l"(*reinterpret_cast<unsigned long long*>(&c)));
    return d;
}

// ---------------------------------------------------------------------------
// Kernel 1: gx0 = x @ W_ih0^T + b_ih0.
// grid = 512 (256 batches x 2 T-halves), block = 192 (1 thread = 1 gate),
// 3 blocks/SM. Each thread holds its 80-float weight row in 40 float2
// registers; x chunk (40 t x 80 f) staged in SMEM; 4 timesteps in flight.
// ---------------------------------------------------------------------------
__global__ __launch_bounds__(192, 3) void gx0_kernel(
    const float* __restrict__ x,
    const float* __restrict__ W_ih0,
    const float* __restrict__ b_ih0)
{
    __shared__ float xs[40 * Fq];          // 12.8 KB, [t][f] natural layout

    const int g     = threadIdx.x;         // gate 0..191
    const int b     = blockIdx.x >> 1;     // batch
    const int thalf = blockIdx.x & 1;      // T half

    // weight row -> registers, f-paired
    float2 wv[40];
    {
        const float2* Wp = reinterpret_cast<const float2*>(W_ih0 + g * Fq);
        #pragma unroll
        for (int k = 0; k < 40; ++k) wv[k] = Wp[k];
    }
    const float bias = b_ih0[g];

    const float4* xg = reinterpret_cast<const float4*>(x + (size_t)b * Tq * Fq)
                     + thalf * 1000 * 20;
    float* outp = g_gx0 + (size_t)b * Tq * G3q + (size_t)thalf * 1000 * G3q + g;

    for (int c = 0; c < 25; ++c) {         // 25 chunks x 40 t
        // stage x chunk: 3200 floats = 800 float4, coalesced
        const float4* src = xg + c * (40 * Fq / 4);
        #pragma unroll 1
        for (int i = g; i < 800; i += 192)
            reinterpret_cast<float4*>(xs)[i] = src[i];
        __syncthreads();

        #pragma unroll 1
        for (int tg = 0; tg < 10; ++tg) {  // groups of 4 timesteps
            const float4* x0 = reinterpret_cast<const float4*>(&xs[(tg * 4 + 0) * Fq]);
            const float4* x1 = reinterpret_cast<const float4*>(&xs[(tg * 4 + 1) * Fq]);
            const float4* x2 = reinterpret_cast<const float4*>(&xs[(tg * 4 + 2) * Fq]);
            const float4* x3 = reinterpret_cast<const float4*>(&xs[(tg * 4 + 3) * Fq]);
            float2 a0 = make_float2(bias, 0.0f);
            float2 a1 = make_float2(bias, 0.0f);
            float2 a2 = make_float2(bias, 0.0f);
            float2 a3 = make_float2(bias, 0.0f);
            #pragma unroll
            for (int k = 0; k < 20; ++k) {
                float2 wlo = wv[2 * k], whi = wv[2 * k + 1];
                float4 v0 = x0[k];
                a0 = ffma2(wlo, make_float2(v0.x, v0.y), a0);
                a0 = ffma2(whi, make_float2(v0.z, v0.w), a0);
                float4 v1 = x1[k];
                a1 = ffma2(wlo, make_float2(v1.x, v1.y), a1);
                a1 = ffma2(whi, make_float2(v1.z, v1.w), a1);
                float4 v2 = x2[k];
                a2 = ffma2(wlo, make_float2(v2.x, v2.y), a2);
                a2 = ffma2(whi, make_float2(v2.z, v2.w), a2);
                float4 v3 = x3[k];
                a3 = ffma2(wlo, make_float2(v3.x, v3.y), a3);
                a3 = ffma2(whi, make_float2(v3.z, v3.w), a3);
            }
            int tbase = c * 40 + tg * 4;
            outp[(size_t)(tbase + 0) * G3q] = a0.x + a0.y;
            outp[(size_t)(tbase + 1) * G3q] = a1.x + a1.y;
            outp[(size_t)(tbase + 2) * G3q] = a2.x + a2.y;
            outp[(size_t)(tbase + 3) * G3q] = a3.x + a3.y;
        }
        __syncthreads();
    }
}

// ---------------------------------------------------------------------------
// Kernel 2: fused 2-layer GRU + FC (R7 winner, byte-identical core):
// gate-owner threads, register weights, shfl reduction, one __syncthreads/step.
//   tid   0..127: L0, j = tid>>1, seg = tid&1  (K half; act batch = seg)
//   tid 128..383: L1, j = (tid-128)>>2, seg = (tid-128)&3 (concat quarter)
// ---------------------------------------------------------------------------
__global__ __launch_bounds__(384, 1) void rnn_kernel(
    const float* __restrict__ h_in,
    const float* __restrict__ W_hh0, const float* __restrict__ b_hh0,
    const float* __restrict__ W_ih1, const float* __restrict__ W_hh1,
    const float* __restrict__ b_ih1, const float* __restrict__ b_hh1,
    const float* __restrict__ W_fc,  const float* __restrict__ b_fc,
    float* __restrict__ out, int write_hidden)
{
    // [parity][batch][quarter of concat [h0;h1]][32 + 8 pad]
    __shared__ float hbuf[2][2][4][40];

    const int tid  = threadIdx.x;
    const int b0   = blockIdx.x * 2;
    const bool isL0 = tid < 128;
    int j, seg;
    if (isL0) { j = tid >> 1; seg = tid & 1; }
    else      { int t = tid - 128; j = t >> 2; seg = t & 3; }

    // --- weight rows (r,z,n) for this thread's K window -> registers ---
    float4 wR[8], wZ[8], wN[8];
    {
        const float4* W;
        int k0;
        if (isL0)          { W = (const float4*)W_hh0; k0 = seg * 8; }
        else if (seg < 2)  { W = (const float4*)W_ih1; k0 = seg * 8; }
        else               { W = (const float4*)W_hh1; k0 = (seg - 2) * 8; }
        #pragma unroll
        for (int k = 0; k < 8; ++k) {
            wR[k] = W[(j      ) * 16 + k0 + k];
            wZ[k] = W[(64 + j ) * 16 + k0 + k];
            wN[k] = W[(128 + j) * 16 + k0 + k];
        }
    }
    // --- biases (act role) ---
    float bR, bZ, bNi = 0.0f, bNh;
    if (isL0) {
        bR = b_hh0[j]; bZ = b_hh0[64 + j]; bNh = b_hh0[128 + j];
    } else {
        bR  = b_ih1[j] + b_hh1[j];
        bZ  = b_ih1[64 + j] + b_hh1[64 + j];
        bNi = b_ih1[128 + j]; bNh = b_hh1[128 + j];
    }

    // --- init state: h0^0 -> buf0 q0/q1 ; h1^0 -> buf1 q2/q3 ; rest zero ---
    if (tid < 256) {
        int b = tid >> 7, idx = tid & 127;
        if (idx < 64) {
            hbuf[0][b][idx >> 5][idx & 31] = h_in[(b0 + b) * Hq + idx];
            hbuf[1][b][idx >> 5][idx & 31] = 0.0f;
        } else {
            int jj = idx - 64;
            hbuf[1][b][2 + (jj >> 5)][jj & 31] = h_in[Bq * Hq + (b0 + b) * Hq + jj];
            hbuf[0][b][2 + (jj >> 5)][jj & 31] = 0.0f;
        }
    }
    __syncthreads();

    // gx stream (L0 act role: batch = seg)
    const float* gxp = g_gx0 + (size_t)(b0 + (seg & 1)) * Tq * G3q;
    float gxR = 0.0f, gxZ = 0.0f, gxN = 0.0f;
    if (isL0 && seg < 2) { gxR = gxp[j]; gxZ = gxp[64 + j]; gxN = gxp[128 + j]; }

    // previous h element owned by this act thread
    float hprev = 0.0f;
    if (isL0 && seg < 2)        hprev = h_in[(b0 + seg) * Hq + j];
    else if (!isL0 && seg < 2)  hprev = h_in[Bq * Hq + (b0 + seg) * Hq + j];

    for (int i = 0; i <= Tq; ++i) {
        const int p = i & 1;

        // prefetch next step's gx (hidden behind the whole step)
        float nR = 0.0f, nZ = 0.0f, nN = 0.0f;
        if (isL0 && seg < 2 && i + 1 < Tq) {
            const float* gq = gxp + (size_t)(i + 1) * G3q;
            nR = __ldg(gq + j); nZ = __ldg(gq + 64 + j); nN = __ldg(gq + 128 + j);
        }

        // --- partial dots over this thread's K window, both batches ---
        const float4* u4 = (const float4*)&hbuf[p][0][seg][0];
        const float4* v4 = (const float4*)&hbuf[p][1][seg][0];
        float2 aR0 = {0,0}, aZ0 = {0,0}, aN0 = {0,0};
        float2 aR1 = {0,0}, aZ1 = {0,0}, aN1 = {0,0};
        #pragma unroll
        for (int k = 0; k < 8; ++k) {
            float4 u = u4[k], v = v4[k];
            float2 ulo = make_float2(u.x, u.y), uhi = make_float2(u.z, u.w);
            float2 vlo = make_float2(v.x, v.y), vhi = make_float2(v.z, v.w);
            float2 rlo = make_float2(wR[k].x, wR[k].y), rhi = make_float2(wR[k].z, wR[k].w);
            float2 zlo = make_float2(wZ[k].x, wZ[k].y), zhi = make_float2(wZ[k].z, wZ[k].w);
            float2 nlo = make_float2(wN[k].x, wN[k].y), nhi = make_float2(wN[k].z, wN[k].w);
            aR0 = ffma2(rlo, ulo, aR0);  aR0 = ffma2(rhi, uhi, aR0);
            aZ0 = ffma2(zlo, ulo, aZ0);  aZ0 = ffma2(zhi, uhi, aZ0);
            aN0 = ffma2(nlo, ulo, aN0);  aN0 = ffma2(nhi, uhi, aN0);
            aR1 = ffma2(rlo, vlo, aR1);  aR1 = ffma2(rhi, vhi, aR1);
            aZ1 = ffma2(zlo, vlo, aZ1);  aZ1 = ffma2(zhi, vhi, aZ1);
            aN1 = ffma2(nlo, vlo, aN1);  aN1 = ffma2(nhi, vhi, aN1);
        }
        float dR0 = aR0.x + aR0.y, dZ0 = aZ0.x + aZ0.y, dN0 = aN0.x + aN0.y;
        float dR1 = aR1.x + aR1.y, dZ1 = aZ1.x + aZ1.y, dN1 = aN1.x + aN1.y;

        if (isL0) {
            dR0 += __shfl_xor_sync(0xffffffffu, dR0, 1);
            dZ0 += __shfl_xor_sync(0xffffffffu, dZ0, 1);
            dN0 += __shfl_xor_sync(0xffffffffu, dN0, 1);
            dR1 += __shfl_xor_sync(0xffffffffu, dR1, 1);
            dZ1 += __shfl_xor_sync(0xffffffffu, dZ1, 1);
            dN1 += __shfl_xor_sync(0xffffffffu, dN1, 1);
            if (i < Tq) {
                float dR = seg ? dR1 : dR0;
                float dZ = seg ? dZ1 : dZ0;
                float dN = seg ? dN1 : dN0;
                float r = siga(gxR + dR + bR);
                float z = siga(gxZ + dZ + bZ);
                float n = tanha(fmaf(r, dN + bNh, gxN));   // gxN includes b_ih0
                float hn = (1.0f - z) * n + z * hprev;
                hprev = hn;
                hbuf[p ^ 1][seg][j >> 5][j & 31] = hn;
            }
            gxR = nR; gxZ = nZ; gxN = nN;
        } else {
            dR0 += __shfl_xor_sync(0xffffffffu, dR0, 1);
            dZ0 += __shfl_xor_sync(0xffffffffu, dZ0, 1);
            dN0 += __shfl_xor_sync(0xffffffffu, dN0, 1);
            dR1 += __shfl_xor_sync(0xffffffffu, dR1, 1);
            dZ1 += __shfl_xor_sync(0xffffffffu, dZ1, 1);
            dN1 += __shfl_xor_sync(0xffffffffu, dN1, 1);
            float oR0 = __shfl_xor_sync(0xffffffffu, dR0, 2);
            float oZ0 = __shfl_xor_sync(0xffffffffu, dZ0, 2);
            float oN0 = __shfl_xor_sync(0xffffffffu, dN0, 2);
            float oR1 = __shfl_xor_sync(0xffffffffu, dR1, 2);
            float oZ1 = __shfl_xor_sync(0xffffffffu, dZ1, 2);
            float oN1 = __shfl_xor_sync(0xffffffffu, dN1, 2);
            dR0 += oR0; dZ0 += oZ0;
            dR1 += oR1; dZ1 += oZ1;
            if (i > 0 && seg < 2) {
                float dR  = seg ? dR1 : dR0;
                float dZ  = seg ? dZ1 : dZ0;
                float dNx = seg ? dN1 : dN0;
                float dNh = seg ? oN1 : oN0;
                float r = siga(dR + bR);
                float z = siga(dZ + bZ);
                float n = tanha(fmaf(r, dNh + bNh, dNx + bNi));
                float hn = (1.0f - z) * n + z * hprev;
                hprev = hn;
                hbuf[p ^ 1][seg][2 + (j >> 5)][j & 31] = hn;
            }
        }
        __syncthreads();   // publish h0^{i+1}, h1^{i} for next iteration
    }

    // ---- epilogue: h0 final in buf0 q0/q1, h1 final in buf1 q2/q3 ----
    if (write_hidden && tid < 2 * Hq) {
        int b = tid >> 6, jj = tid & 63;
        out[Bq * Oq + (b0 + b) * Hq + jj]           = hbuf[0][b][jj >> 5][jj & 31];
        out[Bq * Oq + Bq * Hq + (b0 + b) * Hq + jj] = hbuf[1][b][2 + (jj >> 5)][jj & 31];
    }
    if (tid < 2 * Oq) {
        int b = tid / Oq, o = tid - b * Oq;
        float acc = b_fc[o];
        #pragma unroll
        for (int jj = 0; jj < Hq; ++jj)
            acc = fmaf(fmaxf(hbuf[1][b][2 + (jj >> 5)][jj & 31], 0.0f),
                       __ldg(&W_fc[o * Hq + jj]), acc);
        out[(b0 + b) * Oq + o] = acc;
    }
}

// ---------------------------------------------------------------------------
extern "C" void kernel_launch(void* const* d_in, const int* in_sizes, int n_in,
                              void* d_out, int out_size) {
    const float* x     = (const float*)d_in[0];
    const float* h     = (const float*)d_in[1];
    const float* W_ih0 = (const float*)d_in[2];
    const float* W_hh0 = (const float*)d_in[3];
    const float* b_ih0 = (const float*)d_in[4];
    const float* b_hh0 = (const float*)d_in[5];
    const float* W_ih1 = (const float*)d_in[6];
    const float* W_hh1 = (const float*)d_in[7];
    const float* b_ih1 = (const float*)d_in[8];
    const float* b_hh1 = (const float*)d_in[9];
    const float* W_fc  = (const float*)d_in[10];
    const float* b_fc  = (const float*)d_in[11];
    float* out = (float*)d_out;

    gx0_kernel<<<Bq * 2, 192>>>(x, W_ih0, b_ih0);

    int write_hidden = (out_size >= Bq * Oq + 2 * Bq * Hq) ? 1 : 0;
    rnn_kernel<<<Bq / 2, 384>>>(h, W_hh0, b_hh0,
                                W_ih1, W_hh1, b_ih1, b_hh1,
                                W_fc, b_fc, out, write_hidden);
}